// round 4
// baseline (speedup 1.0000x reference)
#include <cuda_runtime.h>

// tokens: int32[4194304], ls: float32[128,2,2], final: float32[2,1] (unused)
// output: float32[2] = row 0 of ordered product of ls[tokens[t]], last token applied twice.

#define TPB 256
#define TOK_PER_THREAD 4
#define TOK_PER_BLOCK (TPB * TOK_PER_THREAD)   // 1024
#define MAX_BLOCKS 4096

__device__ float4 g_part[MAX_BLOCKS];
__device__ unsigned g_count = 0;

// C = A @ B, row-major 2x2 packed in float4 (x=m00, y=m01, z=m10, w=m11)
__device__ __forceinline__ float4 mm2(float4 A, float4 B) {
    float4 C;
    C.x = fmaf(A.x, B.x, A.y * B.z);
    C.y = fmaf(A.x, B.y, A.y * B.w);
    C.z = fmaf(A.z, B.x, A.w * B.z);
    C.w = fmaf(A.z, B.y, A.w * B.w);
    return C;
}

// Order-preserving pairwise warp reduction; lane 0 ends with ordered product.
__device__ __forceinline__ float4 warp_reduce_ordered(float4 M, unsigned lane) {
    #pragma unroll
    for (int off = 1; off < 32; off <<= 1) {
        float4 B;
        B.x = __shfl_down_sync(0xffffffffu, M.x, off);
        B.y = __shfl_down_sync(0xffffffffu, M.y, off);
        B.z = __shfl_down_sync(0xffffffffu, M.z, off);
        B.w = __shfl_down_sync(0xffffffffu, M.w, off);
        if ((lane & (2 * off - 1)) == 0) M = mm2(M, B);
    }
    return M;
}

// Swizzle for the per-thread product array: 4-way max bank conflict on both
// the contiguous write (tid-major) and the strided read (8l+k pattern).
__device__ __forceinline__ unsigned swz(unsigned t) { return t ^ ((t >> 3) & 7u); }

__global__ void __launch_bounds__(TPB)
chain_fused_kernel(const int* __restrict__ tokens,
                   const float* __restrict__ ls,
                   float* __restrict__ out,
                   int n_tokens) {
    __shared__ float4 s_ls[128];      // 2 KB transition table
    __shared__ float4 s_prod[TPB];    // 4 KB per-thread products (swizzled)
    __shared__ float4 s_warp[TPB / 32];
    __shared__ bool   s_is_last;

    const unsigned tid  = threadIdx.x;
    const unsigned lane = tid & 31u;
    const unsigned wid  = tid >> 5;
    const unsigned nblk = gridDim.x;

    // Issue the (fully coalesced) token load before anything else: lane stride
    // is exactly 16B, so each LDG.128 touches the minimum 4 lines.
    const int4 tk = reinterpret_cast<const int4*>(tokens)[blockIdx.x * TPB + tid];

    if (tid < 128) s_ls[tid] = reinterpret_cast<const float4*>(ls)[tid];
    __syncthreads();

    // Phase 1: ordered product of this thread's 4 contiguous tokens.
    float4 M = s_ls[tk.x];
    M = mm2(M, s_ls[tk.y]);
    M = mm2(M, s_ls[tk.z]);
    M = mm2(M, s_ls[tk.w]);
    s_prod[swz(tid)] = M;
    __syncthreads();

    // Phase 2: warp 0 combines the 256 products in order.
    if (wid == 0) {
        // Each lane grabs 8 consecutive products (independent LDS for MLP),
        // chains them, then an ordered shuffle reduce across lanes.
        float4 p0 = s_prod[swz(8 * lane + 0)];
        float4 p1 = s_prod[swz(8 * lane + 1)];
        float4 p2 = s_prod[swz(8 * lane + 2)];
        float4 p3 = s_prod[swz(8 * lane + 3)];
        float4 p4 = s_prod[swz(8 * lane + 4)];
        float4 p5 = s_prod[swz(8 * lane + 5)];
        float4 p6 = s_prod[swz(8 * lane + 6)];
        float4 p7 = s_prod[swz(8 * lane + 7)];
        // tree-combine for shorter dependent chain (order preserved)
        float4 a = mm2(p0, p1), b = mm2(p2, p3), c = mm2(p4, p5), d = mm2(p6, p7);
        float4 P = mm2(mm2(a, b), mm2(c, d));

        P = warp_reduce_ordered(P, lane);
        if (lane == 0) {
            g_part[blockIdx.x] = P;
            __threadfence();
            unsigned old = atomicAdd(&g_count, 1u);
            s_is_last = (old == nblk - 1);
        }
    }
    __syncthreads();

    // Phase 3: last block combines all block partials in order.
    if (s_is_last) {
        __threadfence();
        const int per_thread = (int)(nblk / TPB);   // 4096/256 = 16
        const int base = tid * per_thread;

        float4 P = g_part[base];
        #pragma unroll 4
        for (int i = 1; i < 16; i++) P = mm2(P, g_part[base + i]);

        P = warp_reduce_ordered(P, lane);
        if (lane == 0) s_warp[wid] = P;
        __syncthreads();

        if (tid == 0) {
            float4 R = s_warp[0];
            #pragma unroll
            for (int w = 1; w < TPB / 32; w++) R = mm2(R, s_warp[w]);

            // Faithful to reference: last token's matrix applied a second time.
            int last = tokens[n_tokens - 1];
            R = mm2(R, s_ls[last]);

            out[0] = R.x;   // v = [1,0] @ R -> row 0
            out[1] = R.y;

            __threadfence();
            atomicExch(&g_count, 0u);   // reset for next graph replay
        }
    }
}

extern "C" void kernel_launch(void* const* d_in, const int* in_sizes, int n_in,
                              void* d_out, int out_size) {
    const int*   tokens = (const int*)d_in[0];
    const float* ls     = (const float*)d_in[1];
    float* out = (float*)d_out;

    const int n = in_sizes[0];                 // 4194304
    const int nblocks = n / TOK_PER_BLOCK;     // 4096

    chain_fused_kernel<<<nblocks, TPB>>>(tokens, ls, out, n);
}

// round 5
// speedup vs baseline: 1.2542x; 1.2542x over previous
#include <cuda_runtime.h>

// tokens: int32[4194304], ls: float32[128,2,2], final: float32[2,1] (unused)
// output: float32[2] = row 0 of ordered product of ls[tokens[t]], last token applied twice.

#define TPB 256
#define TOK_PER_THREAD 16
#define TOK_PER_BLOCK (TPB * TOK_PER_THREAD)   // 4096
#define MAX_BLOCKS 4096

__device__ float4 g_part[MAX_BLOCKS];
__device__ unsigned g_count = 0;

// C = A @ B, row-major 2x2 packed in float4 (x=m00, y=m01, z=m10, w=m11)
__device__ __forceinline__ float4 mm2(float4 A, float4 B) {
    float4 C;
    C.x = fmaf(A.x, B.x, A.y * B.z);
    C.y = fmaf(A.x, B.y, A.y * B.w);
    C.z = fmaf(A.z, B.x, A.w * B.z);
    C.w = fmaf(A.z, B.y, A.w * B.w);
    return C;
}

// Order-preserving pairwise warp reduction; lane 0 ends with ordered product.
__device__ __forceinline__ float4 warp_reduce_ordered(float4 M, unsigned lane) {
    #pragma unroll
    for (int off = 1; off < 32; off <<= 1) {
        float4 B;
        B.x = __shfl_down_sync(0xffffffffu, M.x, off);
        B.y = __shfl_down_sync(0xffffffffu, M.y, off);
        B.z = __shfl_down_sync(0xffffffffu, M.z, off);
        B.w = __shfl_down_sync(0xffffffffu, M.w, off);
        if ((lane & (2 * off - 1)) == 0) M = mm2(M, B);
    }
    return M;
}

// 16B-granule swizzle for the staged token buffer: write (stride-256) is
// conflict-free, read (stride-4) becomes ~2-way instead of 16-way.
__device__ __forceinline__ unsigned swz4(unsigned i) { return i ^ ((i >> 3) & 7u); }

__global__ void __launch_bounds__(TPB)
chain_fused_kernel(const int* __restrict__ tokens,
                   const float* __restrict__ ls,
                   float* __restrict__ out,
                   int n_tokens) {
    __shared__ float4 s_ls[128];                       // 2 KB transition table
    __shared__ int4   s_tok[TOK_PER_BLOCK / 4];        // 16 KB staged tokens (swizzled)
    __shared__ float4 s_warp[TPB / 32];
    __shared__ bool   s_is_last;

    const unsigned tid  = threadIdx.x;
    const unsigned lane = tid & 31u;
    const unsigned wid  = tid >> 5;
    const unsigned nblk = gridDim.x;

    // ── Stage: 4 independent, fully-coalesced LDG.128 per thread (MLP=4).
    const int4* __restrict__ tok4 = reinterpret_cast<const int4*>(tokens);
    const unsigned blk_i4 = blockIdx.x * (TOK_PER_BLOCK / 4);
    int4 a0 = tok4[blk_i4 + tid];
    int4 a1 = tok4[blk_i4 + tid + 256];
    int4 a2 = tok4[blk_i4 + tid + 512];
    int4 a3 = tok4[blk_i4 + tid + 768];

    if (tid < 128) s_ls[tid] = reinterpret_cast<const float4*>(ls)[tid];

    s_tok[swz4(tid)]       = a0;
    s_tok[swz4(tid + 256)] = a1;
    s_tok[swz4(tid + 512)] = a2;
    s_tok[swz4(tid + 768)] = a3;
    __syncthreads();

    // ── Phase 1: ordered product of this thread's 16 contiguous tokens,
    //    two independent 8-chains for ILP.
    int4 t0 = s_tok[swz4(4 * tid + 0)];
    int4 t1 = s_tok[swz4(4 * tid + 1)];
    int4 t2 = s_tok[swz4(4 * tid + 2)];
    int4 t3 = s_tok[swz4(4 * tid + 3)];

    float4 A = s_ls[t0.x];
    float4 B = s_ls[t2.x];
    A = mm2(A, s_ls[t0.y]);  B = mm2(B, s_ls[t2.y]);
    A = mm2(A, s_ls[t0.z]);  B = mm2(B, s_ls[t2.z]);
    A = mm2(A, s_ls[t0.w]);  B = mm2(B, s_ls[t2.w]);
    A = mm2(A, s_ls[t1.x]);  B = mm2(B, s_ls[t3.x]);
    A = mm2(A, s_ls[t1.y]);  B = mm2(B, s_ls[t3.y]);
    A = mm2(A, s_ls[t1.z]);  B = mm2(B, s_ls[t3.z]);
    A = mm2(A, s_ls[t1.w]);  B = mm2(B, s_ls[t3.w]);
    float4 M = mm2(A, B);

    // ── Phase 2: ordered block reduction -> one partial per block.
    M = warp_reduce_ordered(M, lane);
    if (lane == 0) s_warp[wid] = M;
    __syncthreads();

    if (tid == 0) {
        float4 R = s_warp[0];
        #pragma unroll
        for (int w = 1; w < TPB / 32; w++) R = mm2(R, s_warp[w]);
        g_part[blockIdx.x] = R;
        __threadfence();                      // publish partial before counting
        unsigned old = atomicAdd(&g_count, 1u);
        s_is_last = (old == nblk - 1);
    }
    __syncthreads();

    // ── Phase 3: last block combines all 1024 partials in order.
    if (s_is_last) {
        __threadfence();
        const int per_thread = (int)(nblk / TPB);   // 1024/256 = 4
        const int base = tid * per_thread;

        float4 P = g_part[base];
        for (int i = 1; i < per_thread; i++) P = mm2(P, g_part[base + i]);

        P = warp_reduce_ordered(P, lane);
        if (lane == 0) s_warp[wid] = P;
        __syncthreads();

        if (tid == 0) {
            float4 R = s_warp[0];
            #pragma unroll
            for (int w = 1; w < TPB / 32; w++) R = mm2(R, s_warp[w]);

            // Faithful to reference: last token's matrix applied a second time.
            int last = tokens[n_tokens - 1];
            R = mm2(R, s_ls[last]);

            out[0] = R.x;   // v = [1,0] @ R -> row 0
            out[1] = R.y;

            atomicExch(&g_count, 0u);   // reset for next graph replay
        }
    }
}

extern "C" void kernel_launch(void* const* d_in, const int* in_sizes, int n_in,
                              void* d_out, int out_size) {
    const int*   tokens = (const int*)d_in[0];
    const float* ls     = (const float*)d_in[1];
    float* out = (float*)d_out;

    const int n = in_sizes[0];                 // 4194304
    const int nblocks = n / TOK_PER_BLOCK;     // 1024

    chain_fused_kernel<<<nblocks, TPB>>>(tokens, ls, out, n);
}

// round 6
// speedup vs baseline: 1.4545x; 1.1597x over previous
#include <cuda_runtime.h>

// tokens: int32[4194304] (values in [0,128)), ls: float32[128,2,2], final (unused)
// output: float32[2] = row 0 of ordered product of ls[tokens[t]], last token applied twice.

#define TPB 256
#define TOK_PER_THREAD 16
#define TOK_PER_BLOCK (TPB * TOK_PER_THREAD)   // 4096
#define MAX_BLOCKS 4096

__device__ float4 g_part[MAX_BLOCKS];
__device__ unsigned g_count = 0;

// C = A @ B, row-major 2x2 packed in float4 (x=m00, y=m01, z=m10, w=m11)
__device__ __forceinline__ float4 mm2(float4 A, float4 B) {
    float4 C;
    C.x = fmaf(A.x, B.x, A.y * B.z);
    C.y = fmaf(A.x, B.y, A.y * B.w);
    C.z = fmaf(A.z, B.x, A.w * B.z);
    C.w = fmaf(A.z, B.y, A.w * B.w);
    return C;
}

// Order-preserving pairwise warp reduction; lane 0 ends with ordered product.
__device__ __forceinline__ float4 warp_reduce_ordered(float4 M, unsigned lane) {
    #pragma unroll
    for (int off = 1; off < 32; off <<= 1) {
        float4 B;
        B.x = __shfl_down_sync(0xffffffffu, M.x, off);
        B.y = __shfl_down_sync(0xffffffffu, M.y, off);
        B.z = __shfl_down_sync(0xffffffffu, M.z, off);
        B.w = __shfl_down_sync(0xffffffffu, M.w, off);
        if ((lane & (2 * off - 1)) == 0) M = mm2(M, B);
    }
    return M;
}

__global__ void __launch_bounds__(TPB)
chain_fused_kernel(const int* __restrict__ tokens,
                   const float* __restrict__ ls,
                   float* __restrict__ out,
                   int n_tokens) {
    // Replicated table: entry j, replica r at byte offset j*128 + r*16.
    // Lane l always reads replica (l&7) -> fixed bank group, 4-way uniform
    // conflict = structural floor (4 cyc per LDS.128 gather).
    __shared__ __align__(16) char  s_tab[128 * 128];      // 16 KB
    __shared__ unsigned            s_pack[TOK_PER_BLOCK / 4]; // 4 KB packed tokens
    __shared__ float4              s_warp[TPB / 32];
    __shared__ bool                s_is_last;

    const unsigned tid  = threadIdx.x;
    const unsigned lane = tid & 31u;
    const unsigned wid  = tid >> 5;
    const unsigned nblk = gridDim.x;

    // ── Stage tokens: 4 coalesced LDG.128 per thread (MLP=4), pack 4 tokens
    //    per 32-bit word (values < 128 fit in a byte).
    const int4* __restrict__ tok4 = reinterpret_cast<const int4*>(tokens);
    const unsigned blk_i4 = blockIdx.x * (TOK_PER_BLOCK / 4);
    int4 a0 = tok4[blk_i4 + tid];
    int4 a1 = tok4[blk_i4 + tid + 256];
    int4 a2 = tok4[blk_i4 + tid + 512];
    int4 a3 = tok4[blk_i4 + tid + 768];

    // ── Build replicated table (conflict-free rotated writes).
    if (tid < 128) {
        float4 e = reinterpret_cast<const float4*>(ls)[tid];
        #pragma unroll
        for (int r = 0; r < 8; r++) {
            unsigned r_eff = (r + tid) & 7u;
            *reinterpret_cast<float4*>(s_tab + tid * 128 + r_eff * 16) = e;
        }
    }

    s_pack[tid]       = (unsigned)a0.x | ((unsigned)a0.y << 8) | ((unsigned)a0.z << 16) | ((unsigned)a0.w << 24);
    s_pack[tid + 256] = (unsigned)a1.x | ((unsigned)a1.y << 8) | ((unsigned)a1.z << 16) | ((unsigned)a1.w << 24);
    s_pack[tid + 512] = (unsigned)a2.x | ((unsigned)a2.y << 8) | ((unsigned)a2.z << 16) | ((unsigned)a2.w << 24);
    s_pack[tid + 768] = (unsigned)a3.x | ((unsigned)a3.y << 8) | ((unsigned)a3.z << 16) | ((unsigned)a3.w << 24);
    __syncthreads();

    // ── Phase 1: this thread's 16 contiguous tokens via ONE LDS.128,
    //    gathers at the conflict floor, two independent 8-chains for ILP.
    const uint4 w = reinterpret_cast<const uint4*>(s_pack)[tid];
    const unsigned rbase = (lane & 7u) * 16u;   // this lane's replica column

    #define TAB(word, sh) (*reinterpret_cast<const float4*>( \
        s_tab + ((((word) >> (sh)) & 127u) << 7) + rbase))

    float4 A = TAB(w.x, 0);
    float4 B = TAB(w.z, 0);
    A = mm2(A, TAB(w.x,  8));  B = mm2(B, TAB(w.z,  8));
    A = mm2(A, TAB(w.x, 16));  B = mm2(B, TAB(w.z, 16));
    A = mm2(A, TAB(w.x, 24));  B = mm2(B, TAB(w.z, 24));
    A = mm2(A, TAB(w.y,  0));  B = mm2(B, TAB(w.w,  0));
    A = mm2(A, TAB(w.y,  8));  B = mm2(B, TAB(w.w,  8));
    A = mm2(A, TAB(w.y, 16));  B = mm2(B, TAB(w.w, 16));
    A = mm2(A, TAB(w.y, 24));  B = mm2(B, TAB(w.w, 24));
    float4 M = mm2(A, B);
    #undef TAB

    // ── Phase 2: ordered block reduction -> one partial per block.
    M = warp_reduce_ordered(M, lane);
    if (lane == 0) s_warp[wid] = M;
    __syncthreads();

    if (tid == 0) {
        float4 R = s_warp[0];
        #pragma unroll
        for (int wI = 1; wI < TPB / 32; wI++) R = mm2(R, s_warp[wI]);
        g_part[blockIdx.x] = R;
        __threadfence();                      // publish partial before counting
        unsigned old = atomicAdd(&g_count, 1u);
        s_is_last = (old == nblk - 1);
    }
    __syncthreads();

    // ── Phase 3: last block combines all 1024 partials in order.
    if (s_is_last) {
        __threadfence();
        const int per_thread = (int)(nblk / TPB);   // 1024/256 = 4
        const int base = tid * per_thread;

        float4 P = g_part[base];
        for (int i = 1; i < per_thread; i++) P = mm2(P, g_part[base + i]);

        P = warp_reduce_ordered(P, lane);
        if (lane == 0) s_warp[wid] = P;
        __syncthreads();

        if (tid == 0) {
            float4 R = s_warp[0];
            #pragma unroll
            for (int wI = 1; wI < TPB / 32; wI++) R = mm2(R, s_warp[wI]);

            // Faithful to reference: last token's matrix applied a second time.
            int last = tokens[n_tokens - 1];
            float4 L = *reinterpret_cast<const float4*>(s_tab + (last << 7));
            R = mm2(R, L);

            out[0] = R.x;   // v = [1,0] @ R -> row 0
            out[1] = R.y;

            atomicExch(&g_count, 0u);   // reset for next graph replay
        }
    }
}

extern "C" void kernel_launch(void* const* d_in, const int* in_sizes, int n_in,
                              void* d_out, int out_size) {
    const int*   tokens = (const int*)d_in[0];
    const float* ls     = (const float*)d_in[1];
    float* out = (float*)d_out;

    const int n = in_sizes[0];                 // 4194304
    const int nblocks = n / TOK_PER_BLOCK;     // 1024

    chain_fused_kernel<<<nblocks, TPB>>>(tokens, ls, out, n);
}